// round 1
// baseline (speedup 1.0000x reference)
#include <cuda_runtime.h>

#define NDIM  512
#define NKNOT 32
#define NDATA 65536

#define DT   64            // dims per block tile
#define TPB  256           // threads per block (64 dims x 4 rows)
#define ROWS_PER_BLOCK 128

// Precomputed knot tables, knot-major: g_*[k*NDIM + d]
__device__ float g_xx[NKNOT * NDIM];
__device__ float g_yy[NKNOT * NDIM];
__device__ float g_dd[NKNOT * NDIM];

// ---------------------------------------------------------------------------
// Prep: params -> knot positions (cumsum of exp), knot values, derivatives.
// One thread per dim; serial cumsum matches jnp.cumsum ordering.
// ---------------------------------------------------------------------------
__global__ void prep_kernel(const float* __restrict__ params) {
    int d = blockIdx.x * blockDim.x + threadIdx.x;
    if (d >= NDIM) return;

    const float* logdx   = params + 2 * NDIM + d * (NKNOT - 1);
    const float* logdy   = params + 2 * NDIM + NDIM * (NKNOT - 1) + d * (NKNOT - 1);
    const float* logderiv= params + 2 * NDIM + 2 * NDIM * (NKNOT - 1) + d * NKNOT;

    float xx = params[d];
    float yy = params[NDIM + d];
    g_xx[d] = xx;
    g_yy[d] = yy;
    g_dd[d] = expf(logderiv[0]);
    #pragma unroll
    for (int k = 1; k < NKNOT; k++) {
        xx += expf(logdx[k - 1]);
        yy += expf(logdy[k - 1]);
        g_xx[k * NDIM + d] = xx;
        g_yy[k * NDIM + d] = yy;
        g_dd[k * NDIM + d] = expf(logderiv[k]);
    }
}

// ---------------------------------------------------------------------------
// Main: each block owns a 64-dim tile (tables in smem, [knot][dim] layout ->
// bank = d%32, conflict-free for every data-dependent knot index) and a
// 128-row slab. Warps cover 32 consecutive dims -> coalesced x/y/ld traffic.
// ---------------------------------------------------------------------------
__global__ __launch_bounds__(TPB) void spline_kernel(
    const float* __restrict__ x, float* __restrict__ out)
{
    __shared__ float sxx[NKNOT * DT];
    __shared__ float syy[NKNOT * DT];
    __shared__ float sdd[NKNOT * DT];

    const int dbase = blockIdx.x * DT;
    const int tid = threadIdx.x;

    // Load the 64-dim table tile (coalesced from knot-major globals).
    #pragma unroll
    for (int i = tid; i < NKNOT * DT; i += TPB) {
        int k  = i >> 6;        // i / DT
        int dd = i & (DT - 1);  // i % DT
        int g  = k * NDIM + dbase + dd;
        sxx[i] = g_xx[g];
        syy[i] = g_yy[g];
        sdd[i] = g_dd[g];
    }
    __syncthreads();

    const int d  = tid & (DT - 1);
    const int rl = tid >> 6;                       // 0..3
    const int r0 = blockIdx.y * ROWS_PER_BLOCK;

    float* __restrict__ yout  = out;
    float* __restrict__ ldout = out + (size_t)NDATA * NDIM;

    const float xx_last = sxx[(NKNOT - 1) * DT + d];

    for (int rr = rl; rr < ROWS_PER_BLOCK; rr += TPB / DT) {
        const int r = r0 + rr;
        const size_t off = (size_t)r * NDIM + dbase + d;
        const float xv = x[off];

        // Branchless lower bound: base = min(#knots < xv, 31)
        int base = 0;
        #pragma unroll
        for (int s = 16; s > 0; s >>= 1)
            if (sxx[(base + s - 1) * DT + d] < xv) base += s;

        const bool sel0 = (base == 0);        // index == 0
        const bool selN = (xx_last < xv);     // index == NKNOT

        const int ic = (base < 1) ? 1 : base; // clip(index, 1, 31)
        const int lo = (ic - 1) * DT + d;
        const int hi = ic * DT + d;
        const float x_lo = sxx[lo], x_hi = sxx[hi];
        const float y_lo = syy[lo], y_hi = syy[hi];
        const float dl   = sdd[lo], dh   = sdd[hi];

        float yv, ldv;
        if (sel0) {                       // linear tail below first knot
            yv  = fmaf(xv - x_lo, dl, y_lo);
            ldv = __logf(dl);
        } else if (selN) {                // linear tail above last knot
            yv  = fmaf(xv - x_hi, dh, y_hi);
            ldv = __logf(dh);
        } else {                          // rational-quadratic mid branch
            const float inv_dx = __fdividef(1.0f, x_hi - x_lo);
            const float xi   = (xv - x_lo) * inv_dx;   // in (0, 1]
            const float dy   = y_hi - y_lo;
            const float s    = dy * inv_dx;
            const float omxi = 1.0f - xi;
            const float xi1  = xi * omxi;
            const float xi2  = xi * xi;
            const float den  = fmaf(dh + dl - 2.0f * s, xi1, s);  // > 0 always
            const float inv_den = __fdividef(1.0f, den);
            yv = fmaf(dy * fmaf(s, xi2, dl * xi1), inv_den, y_lo);
            // 2*log(s) + log(num) - 2*log(den) = log((s/den)^2 * num)
            const float num = fmaf(dh, xi2, fmaf(2.0f * s, xi1, dl * omxi * omxi));
            const float rs  = s * inv_den;
            ldv = __logf(rs * rs * num);
        }

        yout[off]  = yv;
        ldout[off] = ldv;
    }
}

extern "C" void kernel_launch(void* const* d_in, const int* in_sizes, int n_in,
                              void* d_out, int out_size) {
    const float* x      = (const float*)d_in[0];
    const float* params = (const float*)d_in[1];
    float* out = (float*)d_out;

    prep_kernel<<<(NDIM + 255) / 256, 256>>>(params);

    dim3 grid(NDIM / DT, NDATA / ROWS_PER_BLOCK);
    spline_kernel<<<grid, TPB>>>(x, out);
}

// round 2
// speedup vs baseline: 1.2141x; 1.2141x over previous
#include <cuda_runtime.h>
#include <math_constants.h>

#define NDIM  512
#define NKNOT 32
#define NDATA 65536

#define DT   32            // dims per block tile (one warp-width)
#define TPB  256           // 32 dims x 8 rows per iteration
#define RPB  256           // rows per block

// Packed per-knot record {xx, yy, dd, pad}, knot-major: g_K[k*NDIM + d]
__device__ float4 g_K[NKNOT * NDIM];
// Level-1 pivots per dim: {xx[7], xx[15], xx[23], +inf}
__device__ float4 g_P1[NDIM];
// Level-2 pivots per (quadrant, dim): {xx[8q+1], xx[8q+3], xx[8q+5], 0}
__device__ float4 g_P2[4 * NDIM];
// Even-index knot positions: g_XE[j*NDIM + d] = xx[2j]
__device__ float g_XE[(NKNOT / 2) * NDIM];

// ---------------------------------------------------------------------------
// Prep: params -> packed knot tables + search pivot tables.
// ---------------------------------------------------------------------------
__global__ void prep_kernel(const float* __restrict__ params) {
    int d = blockIdx.x * blockDim.x + threadIdx.x;
    if (d >= NDIM) return;

    const float* logdx    = params + 2 * NDIM + d * (NKNOT - 1);
    const float* logdy    = params + 2 * NDIM + NDIM * (NKNOT - 1) + d * (NKNOT - 1);
    const float* logderiv = params + 2 * NDIM + 2 * NDIM * (NKNOT - 1) + d * NKNOT;

    float xx[NKNOT], yy[NKNOT], dd[NKNOT];
    xx[0] = params[d];
    yy[0] = params[NDIM + d];
    dd[0] = expf(logderiv[0]);
    #pragma unroll
    for (int k = 1; k < NKNOT; k++) {
        xx[k] = xx[k - 1] + expf(logdx[k - 1]);
        yy[k] = yy[k - 1] + expf(logdy[k - 1]);
        dd[k] = expf(logderiv[k]);
    }

    #pragma unroll
    for (int k = 0; k < NKNOT; k++)
        g_K[k * NDIM + d] = make_float4(xx[k], yy[k], dd[k], 0.0f);

    g_P1[d] = make_float4(xx[7], xx[15], xx[23], CUDART_INF_F);

    #pragma unroll
    for (int q = 0; q < 4; q++)
        g_P2[q * NDIM + d] = make_float4(xx[8 * q + 1], xx[8 * q + 3], xx[8 * q + 5], 0.0f);

    #pragma unroll
    for (int j = 0; j < NKNOT / 2; j++)
        g_XE[j * NDIM + d] = xx[2 * j];
}

// ---------------------------------------------------------------------------
// Main kernel. Per block: 32-dim tile, 256-row slab. Search = 4-ary
// tournament (L1 pivots hoisted to registers, L2 one LDS.128, L3 one LDS),
// gathers = 2x LDS.128 from packed records. All smem accesses conflict-free.
// ---------------------------------------------------------------------------
__global__ __launch_bounds__(TPB) void spline_kernel(
    const float* __restrict__ x, float* __restrict__ out)
{
    __shared__ float4 sK[NKNOT * DT];
    __shared__ float4 sP1[DT];
    __shared__ float4 sP2[4 * DT];
    __shared__ float  sXE[(NKNOT / 2) * DT];

    const int dbase = blockIdx.x * DT;
    const int tid = threadIdx.x;

    // Coalesced table-tile fills.
    #pragma unroll
    for (int i = tid; i < NKNOT * DT; i += TPB)
        sK[i] = g_K[(i >> 5) * NDIM + dbase + (i & 31)];
    if (tid < 4 * DT)
        sP2[tid] = g_P2[(tid >> 5) * NDIM + dbase + (tid & 31)];
    else if (tid < 4 * DT + DT)
        sP1[tid - 4 * DT] = g_P1[dbase + (tid - 4 * DT)];
    #pragma unroll
    for (int i = tid; i < (NKNOT / 2) * DT; i += TPB)
        sXE[i] = g_XE[(i >> 5) * NDIM + dbase + (i & 31)];
    __syncthreads();

    const int d  = tid & 31;
    const int rl = tid >> 5;                     // 0..7
    const int r0 = blockIdx.y * RPB;

    float* __restrict__ yout  = out;
    float* __restrict__ ldout = out + (size_t)NDATA * NDIM;

    // Per-thread constants (hoisted out of the row loop).
    const float4 p1     = sP1[d];
    const float  xxlast = sK[(NKNOT - 1) * DT + d].x;

    #pragma unroll 4
    for (int rr = rl; rr < RPB; rr += TPB / DT) {
        const size_t off = (size_t)(r0 + rr) * NDIM + dbase + d;
        const float xv = x[off];

        // --- 4-ary tournament lower bound: base = min(#knots < xv, 31) ---
        int q = (p1.x < xv) + (p1.y < xv) + (p1.z < xv);        // quadrant (0..3)
        const float4 p2 = sP2[q * DT + d];
        int t = (p2.x < xv) + (p2.y < xv) + (p2.z < xv);        // 0..3
        const int j = 4 * q + t;                                 // = base >> 1
        const int base = 2 * j + (sXE[j * DT + d] < xv);         // 0..31

        const bool sel0 = (base == 0);       // index == 0       (low tail)
        const bool selN = (xxlast < xv);     // index == NKNOT   (high tail)

        const int ic = base > 1 ? base : 1;  // clip(index, 1, 31)
        const float4 klo = sK[(ic - 1) * DT + d];
        const float4 khi = sK[ic * DT + d];  // same address + 512B (imm offset)

        const float x_lo = klo.x, y_lo = klo.y, dl = klo.z;
        const float x_hi = khi.x, y_hi = khi.y, dh = khi.z;

        // --- rational-quadratic mid branch (NaN-free via clip) ---
        const float xc     = fminf(fmaxf(xv, x_lo), x_hi);
        const float inv_dx = __fdividef(1.0f, x_hi - x_lo);
        const float xi     = (xc - x_lo) * inv_dx;
        const float dy     = y_hi - y_lo;
        const float s      = dy * inv_dx;
        const float omxi   = 1.0f - xi;
        const float xi1    = xi * omxi;
        const float xi2    = xi * xi;
        const float den    = fmaf(dh + dl - 2.0f * s, xi1, s);   // > 0 always
        const float inv_den = __fdividef(1.0f, den);
        const float y_mid  = fmaf(dy * fmaf(s, xi2, dl * xi1), inv_den, y_lo);
        const float num    = fmaf(dh, xi2, fmaf(2.0f * s, xi1, dl * omxi * omxi));
        const float rs     = s * inv_den;

        // --- branchless tail selection ---
        float yv = y_mid;
        float larg = rs * rs * num;          // 2log(s)+log(num)-2log(den)
        if (selN) { yv = fmaf(xv - x_hi, dh, y_hi); larg = dh; }
        if (sel0) { yv = fmaf(xv - x_lo, dl, y_lo); larg = dl; }
        const float ldv = __logf(larg);

        yout[off]  = yv;
        ldout[off] = ldv;
    }
}

extern "C" void kernel_launch(void* const* d_in, const int* in_sizes, int n_in,
                              void* d_out, int out_size) {
    const float* x      = (const float*)d_in[0];
    const float* params = (const float*)d_in[1];
    float* out = (float*)d_out;

    prep_kernel<<<(NDIM + 255) / 256, 256>>>(params);

    dim3 grid(NDIM / DT, NDATA / RPB);
    spline_kernel<<<grid, TPB>>>(x, out);
}